// round 12
// baseline (speedup 1.0000x reference)
#include <cuda_runtime.h>
#include <math.h>

// ---------------------------------------------------------------------------
// UncertaintyWeightedLoss — persistent fused kernel; branch-free hot loop.
//   phase A: CTA 0,1 scan counts -> g_off (full-unroll int4 loads); other
//            CTAs do a small note-MSE slice meanwhile.
//   phase B: all CTAs persistent CE: 8 warps, 2-stage cp.async ring with
//            ZFILL padding (no predication anywhere in the steady loop),
//            single-pass direct sum-exp (f32x2 scale), pad-corrected Z,
//            lg2.approx-based CE, __all_sync argmax shortcut.
//   last CTA (ticket): reduce per-CTA partials, 9 outputs, reset state.
// ---------------------------------------------------------------------------

#define MAXB 16384
#define K4   5                    // float4 slots/lane per stage
#define BUFE 640                  // floats per stage (5*32*4, zfill-padded)
#define NWARP 8
#define MAXCTA 2048
#define L2E 1.4426950408889634f
#define LN2 0.6931471805599453f

__device__ int           g_off[2][MAXB];
__device__ double        g_part_ce_s[MAXCTA];
__device__ double        g_part_ce_b[MAXCTA];
__device__ uint2         g_part_cnt[MAXCTA];
__device__ double        g_note_sq[MAXCTA];
__device__ double        g_note_ns[MAXCTA];
__device__ unsigned int  g_done;
__device__ unsigned int  g_scan_done;

__device__ __forceinline__ float ex2f(float x) {
    float r;
    asm("ex2.approx.f32 %0, %1;" : "=f"(r) : "f"(x));
    return r;
}
__device__ __forceinline__ float lg2f(float x) {
    float r;
    asm("lg2.approx.f32 %0, %1;" : "=f"(r) : "f"(x));
    return r;
}
// packed f32x2 multiply by log2(e): (x,y) -> (x*L2E, y*L2E)
__device__ __forceinline__ float2 mul2l2e(float x, float y) {
    unsigned long long p, r;
    asm("mov.b64 %0, {%1, %2};" : "=l"(p) : "f"(x), "f"(y));
    asm("mul.rn.f32x2 %0, %1, %2;" : "=l"(r)
        : "l"(p), "l"(0x3FB8AA3B3FB8AA3BULL));
    float lo, hi;
    asm("mov.b64 {%0, %1}, %2;" : "=f"(lo), "=f"(hi) : "l"(r));
    return make_float2(lo, hi);
}
__device__ __forceinline__ unsigned int ldacq(const unsigned int* p) {
    unsigned int v;
    asm volatile("ld.acquire.gpu.u32 %0, [%1];" : "=r"(v) : "l"(p) : "memory");
    return v;
}
// cp.async with runtime src-size (zero-fills dst tail) — branch-free OOB
__device__ __forceinline__ void cpasync16z(unsigned int saddr, const void* gaddr,
                                           int srcbytes) {
    asm volatile("cp.async.cg.shared.global [%0], [%1], 16, %2;"
                 :: "r"(saddr), "l"(gaddr), "r"(srcbytes));
}
__device__ __forceinline__ void cpcommit() {
    asm volatile("cp.async.commit_group;");
}
__device__ __forceinline__ void cpwait1() {
    asm volatile("cp.async.wait_group 1;");
}
__device__ __forceinline__ float wsum(float v) {
    #pragma unroll
    for (int o = 16; o; o >>= 1) v += __shfl_xor_sync(0xffffffffu, v, o);
    return v;
}
__device__ __forceinline__ int wmin(int v) {
    #pragma unroll
    for (int o = 16; o; o >>= 1) v = min(v, __shfl_xor_sync(0xffffffffu, v, o));
    return v;
}
__device__ __forceinline__ double wsumd(double v) {
    #pragma unroll
    for (int o = 16; o; o >>= 1) v += __shfl_xor_sync(0xffffffffu, v, o);
    return v;
}
__device__ __forceinline__ double blk_sum256(double v, double* s) {
    int t = threadIdx.x;
    s[t] = v;
    __syncthreads();
    #pragma unroll
    for (int k = 128; k > 0; k >>= 1) {
        if (t < k) s[t] += s[t + k];
        __syncthreads();
    }
    double r = s[0];
    __syncthreads();
    return r;
}

// prefix scan for one task, 256 threads, int4, FULLY unrolled loads (MLP 16)
__device__ void do_scan(const int* __restrict__ counts, int* __restrict__ offs,
                        int Bn, int* wtot) {
    int t = threadIdx.x, lane = t & 31, wid = t >> 5;
    int CH = (Bn + 255) >> 8;
    int base = t * CH;
    bool vec = ((CH & 3) == 0) && (base + CH <= Bn) && (CH <= 64);

    int sum = 0;
    if (vec) {
        const int4* p = (const int4*)(counts + base);
        int q4 = CH >> 2;
        int4 v[16];
        #pragma unroll 16
        for (int q = 0; q < 16; ++q)
            if (q < q4) v[q] = p[q];
        #pragma unroll 16
        for (int q = 0; q < 16; ++q)
            if (q < q4) sum += (v[q].x + v[q].y) + (v[q].z + v[q].w);
        int incl = sum;
        #pragma unroll
        for (int o = 1; o < 32; o <<= 1) {
            int u = __shfl_up_sync(0xffffffffu, incl, o);
            if (lane >= o) incl += u;
        }
        if (lane == 31) wtot[wid] = incl;
        __syncthreads();
        if (wid == 0 && lane < 8) {
            int x = wtot[lane];
            #pragma unroll
            for (int o = 1; o < 8; o <<= 1) {
                int u = __shfl_up_sync(0x000000ffu, x, o);
                if (lane >= o) x += u;
            }
            wtot[lane] = x;
        }
        __syncthreads();
        int wbase = (wid == 0) ? 0 : wtot[wid - 1];
        int run = wbase + incl - sum;
        int4* po = (int4*)(offs + base);
        #pragma unroll 16
        for (int q = 0; q < 16; ++q) {
            if (q < q4) {
                int4 o;
                o.x = run; run += v[q].x;
                o.y = run; run += v[q].y;
                o.z = run; run += v[q].z;
                o.w = run; run += v[q].w;
                po[q] = o;
            }
        }
    } else {
        for (int k = 0; k < CH; ++k) {
            int idx = base + k;
            if (idx < Bn) sum += counts[idx];
        }
        int incl = sum;
        #pragma unroll
        for (int o = 1; o < 32; o <<= 1) {
            int u = __shfl_up_sync(0xffffffffu, incl, o);
            if (lane >= o) incl += u;
        }
        if (lane == 31) wtot[wid] = incl;
        __syncthreads();
        if (wid == 0 && lane < 8) {
            int x = wtot[lane];
            #pragma unroll
            for (int o = 1; o < 8; o <<= 1) {
                int u = __shfl_up_sync(0x000000ffu, x, o);
                if (lane >= o) x += u;
            }
            wtot[lane] = x;
        }
        __syncthreads();
        int wbase = (wid == 0) ? 0 : wtot[wid - 1];
        int run = wbase + incl - sum;
        for (int k = 0; k < CH; ++k) {
            int idx = base + k;
            if (idx < Bn) { offs[idx] = run; run += counts[idx]; }
        }
    }
}

__global__ __launch_bounds__(256, 5) void fused_kernel(
    const float* __restrict__ sys_logits, const float* __restrict__ bar_logits,
    const int* __restrict__ sys_counts,   const int* __restrict__ bar_counts,
    const int* __restrict__ gt_sys,       const int* __restrict__ gt_bar,
    const int* __restrict__ valid,
    const float* __restrict__ notep,      const float* __restrict__ gtnote,
    const float* __restrict__ lv_sys,     const float* __restrict__ lv_bar,
    const float* __restrict__ lv_note,
    int Bn, float* __restrict__ out) {

    __shared__ float  ring[NWARP][2][BUFE];       // 40 KB zfill staging
    __shared__ double sbuf[256];
    __shared__ int    wtot[8];
    __shared__ float  s_ce[2][NWARP];
    __shared__ int    s_nv[2][NWARP], s_co[2][NWARP];
    __shared__ unsigned int ticket;

    int cta = blockIdx.x;
    int grid = gridDim.x;
    int t = threadIdx.x;
    int lane = t & 31;
    int w = t >> 5;
    const float NEGINF = __int_as_float(0xff800000);

    // ---------------- phase A ----------------
    if (cta < 2) {
        do_scan(cta == 0 ? sys_counts : bar_counts, g_off[cta], Bn, wtot);
        __threadfence();
        __syncthreads();
        if (t == 0) {
            atomicAdd(&g_scan_done, 1u);
            g_note_sq[cta] = 0.0;
            g_note_ns[cta] = 0.0;
        }
    } else {
        int chunk = (Bn + grid - 3) / (grid - 2);
        if (w == 0) {
            double sq = 0.0, ns = 0.0;
            int base = (cta - 2) * chunk;
            for (int j = lane; j < chunk; j += 32) {
                int i = base + j;
                if (i < Bn && valid[i] != 0) {
                    double d = (double)notep[i] - (double)gtnote[i];
                    sq += d * d;
                    ns += 1.0;
                }
            }
            sq = wsumd(sq);
            ns = wsumd(ns);
            if (lane == 0) { g_note_sq[cta] = sq; g_note_ns[cta] = ns; }
        }
    }

    // ---------------- phase B: persistent CE (ALL CTAs) ----------------
    {
        int tot = 2 * Bn;
        int W = grid * NWARP;
        int gw = cta * NWARP + w;

        float ces = 0.0f, ceb = 0.0f;
        int nvs = 0, cos_ = 0, nvb = 0, cob = 0;

        unsigned int shb[2];
        shb[0] = (unsigned int)__cvta_generic_to_shared(&ring[w][0][0]);
        shb[1] = (unsigned int)__cvta_generic_to_shared(&ring[w][1][0]);

        // prologue: lane r holds round-r meta
        int msl = gw + lane * W;
        int mtask = (msl >= Bn) ? 1 : 0;
        int mb = msl - mtask * Bn;
        int mc = 0, mg = 0, mv = 0, mo = 0;
        bool mok = (msl < tot);
        if (mok) {
            mc = mtask ? bar_counts[mb] : sys_counts[mb];
            mg = mtask ? gt_bar[mb] : gt_sys[mb];
            mv = valid[mb];
        }
        if (t == 0) {
            while (ldacq(&g_scan_done) < 2u) __nanosleep(64);
        }
        __syncthreads();
        if (mok) mo = __ldcg(&g_off[mtask][mb]);

        auto getmeta = [&](int r, int& c, int& o, int& g, int& v) {
            c = __shfl_sync(0xffffffffu, mc, r);
            o = __shfl_sync(0xffffffffu, mo, r);
            g = __shfl_sync(0xffffffffu, mg, r);
            v = __shfl_sync(0xffffffffu, mv, r);
        };
        // branch-free issue: 5 zfill cp.asyncs, clamped address + size
        auto issue = [&](int p, int s, int c, int o) {
            if (s < tot && ((o | c) & 3) == 0 && c <= BUFE) {
                const float* ptr = (s >= Bn) ? bar_logits : sys_logits;
                const float4* src = (const float4*)(ptr + o);
                int c4 = c >> 2;
                unsigned int base = shb[p];
                #pragma unroll
                for (int k = 0; k < K4; ++k) {
                    int vi = lane + (k << 5);
                    int sz = min(max((c4 - vi) << 4, 0), 16);
                    int ai = min(vi, max(c4 - 1, 0));
                    cpasync16z(base + vi * 16, src + ai, sz);
                }
            }
            cpcommit();
        };
        auto process = [&](int p, int s, int c, int o, int g, int vld) {
            if (s >= tot) return;
            int task = (s >= Bn) ? 1 : 0;
            float Z, tlogit;
            bool cor;
            if (((o | c) & 3) == 0 && c <= BUFE) {
                const float4* sb = (const float4*)&ring[w][p][0];
                // fully unconditional: tail is zero-filled (exp(0)=1,
                // corrected below); no predicates, no branches.
                float s0 = 0.f, s1 = 0.f, s2 = 0.f, s3 = 0.f;
                float m0 = NEGINF, m1 = NEGINF, m2 = NEGINF, m3 = NEGINF;
                #pragma unroll
                for (int k = 0; k < K4; ++k) {
                    float4 v = sb[lane + (k << 5)];
                    float2 a0 = mul2l2e(v.x, v.y);
                    float2 a1 = mul2l2e(v.z, v.w);
                    s0 += ex2f(a0.x);
                    s1 += ex2f(a0.y);
                    s2 += ex2f(a1.x);
                    s3 += ex2f(a1.y);
                    m0 = fmaxf(m0, v.x);
                    m1 = fmaxf(m1, v.y);
                    m2 = fmaxf(m2, v.z);
                    m3 = fmaxf(m3, v.w);
                }
                float Zr = wsum((s0 + s1) + (s2 + s3));
                Z = Zr - (float)(32 * 4 * K4 - c);       // remove pad ones
                int gi = min(max(g, 0), c > 0 ? c - 1 : 0);
                tlogit = ring[w][p][gi];
                float mym = fmaxf(fmaxf(m0, m1), fmaxf(m2, m3));
                cor = false;
                if (__all_sync(0xffffffffu, mym <= tlogit)) {   // rare
                    int myarg = 0x7fffffff;
                    #pragma unroll
                    for (int k = 0; k < K4; ++k) {
                        float4 v = sb[lane + (k << 5)];
                        int e = (lane + (k << 5)) << 2;
                        if (v.x == tlogit) myarg = min(myarg, e + 0);
                        if (v.y == tlogit) myarg = min(myarg, e + 1);
                        if (v.z == tlogit) myarg = min(myarg, e + 2);
                        if (v.w == tlogit) myarg = min(myarg, e + 3);
                    }
                    myarg = wmin(myarg);
                    cor = (myarg == g) && (myarg < c);
                }
            } else {
                const float* ptr = task ? bar_logits : sys_logits;
                float sm = 0.0f, mymax = NEGINF;
                for (int i = lane; i < c; i += 32) {
                    float v = ptr[o + i];
                    sm += ex2f(v * L2E);
                    mymax = fmaxf(mymax, v);
                }
                Z = wsum(sm);
                tlogit = (g >= 0 && g < c) ? ptr[o + g] : 0.0f;
                cor = false;
                if (__all_sync(0xffffffffu, mymax <= tlogit)) {
                    int arg = 0x7fffffff;
                    for (int i = lane; i < c; i += 32) {
                        if (ptr[o + i] == tlogit) arg = min(arg, i);
                    }
                    cor = (wmin(arg) == g);
                }
            }
            if (lane == 0) {
                bool vmask = (c > 0) && (g >= 0) && (g < c) && (vld != 0);
                if (vmask) {
                    // ln(Z) = lg2(Z) * ln2   (MUFU.LG2 + FFMA, no logf call)
                    float ce = fmaf(lg2f(Z), LN2, -tlogit);
                    int ci = cor ? 1 : 0;
                    if (task) { ceb += ce; nvb += 1; cob += ci; }
                    else      { ces += ce; nvs += 1; cos_ += ci; }
                }
            }
        };

        // 2-deep software pipeline
        int s0 = gw, s1 = gw + W;
        int c0, o0, g0, v0, c1, o1, g1, v1;
        getmeta(0, c0, o0, g0, v0);
        getmeta(1, c1, o1, g1, v1);
        issue(0, s0, c0, o0);
        issue(1, s1, c1, o1);
        int p = 0, r = 2;
        while (s0 < tot) {
            int s2 = s1 + W;
            int c2, o2, g2, v2;
            getmeta(min(r, 31), c2, o2, g2, v2);
            cpwait1();
            process(p, s0, c0, o0, g0, v0);
            issue(p, s2, c2, o2);
            s0 = s1; c0 = c1; o0 = o1; g0 = g1; v0 = v1;
            s1 = s2; c1 = c2; o1 = o2; g1 = g2; v1 = v2;
            p ^= 1;
            ++r;
        }

        if (lane == 0) {
            s_ce[0][w] = ces; s_ce[1][w] = ceb;
            s_nv[0][w] = nvs; s_nv[1][w] = nvb;
            s_co[0][w] = cos_; s_co[1][w] = cob;
        }
        __syncthreads();
        if (t == 0) {
            float tce_s = 0.0f, tce_b = 0.0f;
            int tnv_s = 0, tco_s = 0, tnv_b = 0, tco_b = 0;
            #pragma unroll
            for (int i = 0; i < NWARP; ++i) {
                tce_s += s_ce[0][i]; tce_b += s_ce[1][i];
                tnv_s += s_nv[0][i]; tnv_b += s_nv[1][i];
                tco_s += s_co[0][i]; tco_b += s_co[1][i];
            }
            g_part_ce_s[cta] = (double)tce_s;
            g_part_ce_b[cta] = (double)tce_b;
            g_part_cnt[cta] = make_uint2(
                (unsigned int)tnv_s | ((unsigned int)tco_s << 16),
                (unsigned int)tnv_b | ((unsigned int)tco_b << 16));
        }
    }

    // ---------------- ticket + last-CTA finalize ----------------
    __syncthreads();
    __threadfence();
    if (t == 0) ticket = atomicAdd(&g_done, 1u);
    __syncthreads();
    if (ticket != gridDim.x - 1) return;

    if (t == 0) { g_done = 0; g_scan_done = 0; }

    double ce_s = 0, ce_b = 0, sq = 0, ns = 0;
    int nv_s = 0, co_s = 0, nv_b = 0, co_b = 0;

    for (int i = t; i < grid; i += 256) {
        ce_s += __ldcg(&g_part_ce_s[i]);
        ce_b += __ldcg(&g_part_ce_b[i]);
        uint2 pc = __ldcg(&g_part_cnt[i]);
        nv_s += pc.x & 0xffff; co_s += pc.x >> 16;
        nv_b += pc.y & 0xffff; co_b += pc.y >> 16;
        sq += __ldcg(&g_note_sq[i]);
        ns += __ldcg(&g_note_ns[i]);
    }

    ce_s = blk_sum256(ce_s, sbuf);
    double dnv_s = blk_sum256((double)nv_s, sbuf);
    double dco_s = blk_sum256((double)co_s, sbuf);
    ce_b = blk_sum256(ce_b, sbuf);
    double dnv_b = blk_sum256((double)nv_b, sbuf);
    double dco_b = blk_sum256((double)co_b, sbuf);
    sq = blk_sum256(sq, sbuf);
    ns = blk_sum256(ns, sbuf);

    if (t == 0) {
        double sys_loss  = ce_s / fmax(dnv_s, 1.0);
        double bar_loss  = ce_b / fmax(dnv_b, 1.0);
        double note_loss = (ns > 0.0) ? sq / fmax(ns, 1.0) : 0.0;

        float lvs = lv_sys[0], lvb = lv_bar[0], lvn = lv_note[0];
        float ps = expf(-lvs), pb = expf(-lvb), pn = expf(-lvn);

        double loss = 0.5 * (double)ps * sys_loss + 0.5 * (double)lvs
                    + 0.5 * (double)pb * bar_loss + 0.5 * (double)lvb
                    + 0.5 * (double)pn * note_loss + 0.5 * (double)lvn;

        out[0] = (float)loss;
        out[1] = (float)sys_loss;
        out[2] = (float)bar_loss;
        out[3] = (float)note_loss;
        out[4] = (float)(dco_s / fmax(dnv_s, 1.0));
        out[5] = (float)(dco_b / fmax(dnv_b, 1.0));
        out[6] = ps;
        out[7] = pb;
        out[8] = pn;
    }
}

// ---------------------------------------------------------------------------
extern "C" void kernel_launch(void* const* d_in, const int* in_sizes, int n_in,
                              void* d_out, int out_size) {
    const float* sys_logits = (const float*)d_in[0];
    const int*   sys_counts = (const int*)d_in[1];
    const float* bar_logits = (const float*)d_in[2];
    const int*   bar_counts = (const int*)d_in[3];
    const float* notep      = (const float*)d_in[4];
    const int*   gt_sys     = (const int*)d_in[5];
    const int*   gt_bar     = (const int*)d_in[6];
    const float* gtnote     = (const float*)d_in[7];
    const int*   valid      = (const int*)d_in[8];
    const float* lvs        = (const float*)d_in[9];
    const float* lvb        = (const float*)d_in[10];
    const float* lvn        = (const float*)d_in[11];

    int Bn = in_sizes[1];
    if (Bn > MAXB) Bn = MAXB;

    int grid = 148 * 5;                    // one wave, every CTA does CE
    if (grid > MAXCTA) grid = MAXCTA;

    fused_kernel<<<grid, 256>>>(
        sys_logits, bar_logits, sys_counts, bar_counts, gt_sys, gt_bar, valid,
        notep, gtnote, lvs, lvb, lvn, Bn, (float*)d_out);
}

// round 15
// speedup vs baseline: 1.7551x; 1.7551x over previous
#include <cuda_runtime.h>
#include <math.h>

// ---------------------------------------------------------------------------
// UncertaintyWeightedLoss — persistent fused kernel (best-of merge):
//   phase A: CTA 0,1 scan counts -> g_off; other CTAs do note-MSE slices.
//   phase B: ALL CTAs persistent CE: 8 warps, 2-stage cp.async ring
//            (predicated issue), meta one-lane-per-round (3 shfl/round,
//            validity pre-resolved into ge sentinel), single-pass direct
//            sum-exp, lg2-based CE, __all_sync argmax shortcut (exact).
//   last CTA (ticket): reduce per-CTA partials, 9 outputs, reset state.
// ---------------------------------------------------------------------------

#define MAXB 16384
#define K4   5                    // float4 slots/lane per stage
#define BUFE 640                  // floats per stage
#define NWARP 8
#define MAXCTA 2048
#define L2E 1.4426950408889634f
#define LN2 0.6931471805599453f

__device__ int           g_off[2][MAXB];
__device__ double        g_part_ce_s[MAXCTA];
__device__ double        g_part_ce_b[MAXCTA];
__device__ uint2         g_part_cnt[MAXCTA];
__device__ double        g_note_sq[MAXCTA];
__device__ double        g_note_ns[MAXCTA];
__device__ unsigned int  g_done;
__device__ unsigned int  g_scan_done;

__device__ __forceinline__ float ex2f(float x) {
    float r;
    asm("ex2.approx.f32 %0, %1;" : "=f"(r) : "f"(x));
    return r;
}
__device__ __forceinline__ float lg2f(float x) {
    float r;
    asm("lg2.approx.f32 %0, %1;" : "=f"(r) : "f"(x));
    return r;
}
__device__ __forceinline__ unsigned int ldacq(const unsigned int* p) {
    unsigned int v;
    asm volatile("ld.acquire.gpu.u32 %0, [%1];" : "=r"(v) : "l"(p) : "memory");
    return v;
}
__device__ __forceinline__ void cpasync16(unsigned int saddr, const void* gaddr) {
    asm volatile("cp.async.cg.shared.global [%0], [%1], 16;"
                 :: "r"(saddr), "l"(gaddr));
}
__device__ __forceinline__ void cpcommit() {
    asm volatile("cp.async.commit_group;");
}
__device__ __forceinline__ void cpwait1() {
    asm volatile("cp.async.wait_group 1;");
}
__device__ __forceinline__ float wsum(float v) {
    #pragma unroll
    for (int o = 16; o; o >>= 1) v += __shfl_xor_sync(0xffffffffu, v, o);
    return v;
}
__device__ __forceinline__ int wmin(int v) {
    #pragma unroll
    for (int o = 16; o; o >>= 1) v = min(v, __shfl_xor_sync(0xffffffffu, v, o));
    return v;
}
__device__ __forceinline__ double wsumd(double v) {
    #pragma unroll
    for (int o = 16; o; o >>= 1) v += __shfl_xor_sync(0xffffffffu, v, o);
    return v;
}
__device__ __forceinline__ double blk_sum256(double v, double* s) {
    int t = threadIdx.x;
    s[t] = v;
    __syncthreads();
    #pragma unroll
    for (int k = 128; k > 0; k >>= 1) {
        if (t < k) s[t] += s[t + k];
        __syncthreads();
    }
    double r = s[0];
    __syncthreads();
    return r;
}

// prefix scan for one task, 256 threads, int4-vectorized
__device__ void do_scan(const int* __restrict__ counts, int* __restrict__ offs,
                        int Bn, int* wtot) {
    int t = threadIdx.x, lane = t & 31, wid = t >> 5;
    int CH = (Bn + 255) >> 8;
    int base = t * CH;
    bool vec = ((CH & 3) == 0) && (base + CH <= Bn);

    int sum = 0;
    if (vec) {
        const int4* p = (const int4*)(counts + base);
        int q4 = CH >> 2;
        #pragma unroll 4
        for (int q = 0; q < q4; ++q) {
            int4 v = p[q];
            sum += (v.x + v.y) + (v.z + v.w);
        }
    } else {
        for (int k = 0; k < CH; ++k) {
            int idx = base + k;
            if (idx < Bn) sum += counts[idx];
        }
    }
    int incl = sum;
    #pragma unroll
    for (int o = 1; o < 32; o <<= 1) {
        int v = __shfl_up_sync(0xffffffffu, incl, o);
        if (lane >= o) incl += v;
    }
    if (lane == 31) wtot[wid] = incl;
    __syncthreads();
    if (wid == 0 && lane < 8) {
        int v = wtot[lane];
        #pragma unroll
        for (int o = 1; o < 8; o <<= 1) {
            int u = __shfl_up_sync(0x000000ffu, v, o);
            if (lane >= o) v += u;
        }
        wtot[lane] = v;
    }
    __syncthreads();
    int wbase = (wid == 0) ? 0 : wtot[wid - 1];
    int run = wbase + incl - sum;
    if (vec) {
        const int4* p = (const int4*)(counts + base);
        int4* po = (int4*)(offs + base);
        int q4 = CH >> 2;
        #pragma unroll 4
        for (int q = 0; q < q4; ++q) {
            int4 v = p[q];
            int4 o;
            o.x = run; run += v.x;
            o.y = run; run += v.y;
            o.z = run; run += v.z;
            o.w = run; run += v.w;
            po[q] = o;
        }
    } else {
        for (int k = 0; k < CH; ++k) {
            int idx = base + k;
            if (idx < Bn) { offs[idx] = run; run += counts[idx]; }
        }
    }
}

__global__ __launch_bounds__(256, 4) void fused_kernel(
    const float* __restrict__ sys_logits, const float* __restrict__ bar_logits,
    const int* __restrict__ sys_counts,   const int* __restrict__ bar_counts,
    const int* __restrict__ gt_sys,       const int* __restrict__ gt_bar,
    const int* __restrict__ valid,
    const float* __restrict__ notep,      const float* __restrict__ gtnote,
    const float* __restrict__ lv_sys,     const float* __restrict__ lv_bar,
    const float* __restrict__ lv_note,
    int Bn, float* __restrict__ out) {

    __shared__ float  ring[NWARP][2][BUFE];       // 40 KB staging
    __shared__ double sbuf[256];
    __shared__ int    wtot[8];
    __shared__ float  s_ce[2][NWARP];
    __shared__ int    s_nv[2][NWARP], s_co[2][NWARP];
    __shared__ unsigned int ticket;

    int cta = blockIdx.x;
    int grid = gridDim.x;
    int t = threadIdx.x;
    int lane = t & 31;
    int w = t >> 5;
    const float NEGINF = __int_as_float(0xff800000);

    // ---------------- phase A ----------------
    if (cta < 2) {
        do_scan(cta == 0 ? sys_counts : bar_counts, g_off[cta], Bn, wtot);
        __threadfence();
        __syncthreads();
        if (t == 0) {
            atomicAdd(&g_scan_done, 1u);
            g_note_sq[cta] = 0.0;
            g_note_ns[cta] = 0.0;
        }
    } else {
        int chunk = (Bn + grid - 3) / (grid - 2);
        if (w == 0) {
            double sq = 0.0, ns = 0.0;
            int base = (cta - 2) * chunk;
            for (int j = lane; j < chunk; j += 32) {
                int i = base + j;
                if (i < Bn && valid[i] != 0) {
                    double d = (double)notep[i] - (double)gtnote[i];
                    sq += d * d;
                    ns += 1.0;
                }
            }
            sq = wsumd(sq);
            ns = wsumd(ns);
            if (lane == 0) { g_note_sq[cta] = sq; g_note_ns[cta] = ns; }
        }
    }

    // ---------------- phase B: persistent CE (ALL CTAs) ----------------
    {
        int tot = 2 * Bn;
        int W = grid * NWARP;
        int gw = cta * NWARP + w;

        float ces = 0.0f, ceb = 0.0f;
        int nvs = 0, cos_ = 0, nvb = 0, cob = 0;

        unsigned int shb[2];
        shb[0] = (unsigned int)__cvta_generic_to_shared(&ring[w][0][0]);
        shb[1] = (unsigned int)__cvta_generic_to_shared(&ring[w][1][0]);

        // prologue: lane r holds round-r meta; validity pre-resolved into ge
        int msl = gw + lane * W;
        int mtask = (msl >= Bn) ? 1 : 0;
        int mb = msl - mtask * Bn;
        int mc = 0, mge = -1, mo = 0;
        bool mok = (msl < tot);
        if (mok) {
            mc = mtask ? bar_counts[mb] : sys_counts[mb];
            int g = mtask ? gt_bar[mb] : gt_sys[mb];
            int v = valid[mb];
            // ge >= 0  <=>  this segment contributes (valid & in-range)
            mge = (v != 0 && g >= 0 && g < mc && mc > 0) ? g : -1;
        }
        if (t == 0) {
            while (ldacq(&g_scan_done) < 2u) __nanosleep(64);
        }
        __syncthreads();
        if (mok) mo = __ldcg(&g_off[mtask][mb]);

        auto getmeta = [&](int r, int& c, int& o, int& ge) {
            int rr = min(r, 31);
            c  = __shfl_sync(0xffffffffu, mc, rr);
            o  = __shfl_sync(0xffffffffu, mo, rr);
            ge = __shfl_sync(0xffffffffu, mge, rr);
        };
        auto issue = [&](int p, int s, int c, int o) {
            if (s < tot && ((o | c) & 3) == 0 && c <= BUFE) {
                const float* ptr = (s >= Bn) ? bar_logits : sys_logits;
                const float4* src = (const float4*)(ptr + o);
                int c4 = c >> 2;
                unsigned int base = shb[p];
                #pragma unroll
                for (int k = 0; k < K4; ++k) {
                    int vi = lane + (k << 5);
                    if (vi < c4) cpasync16(base + vi * 16, src + vi);
                }
            }
            cpcommit();
        };
        auto process = [&](int p, int s, int c, int o, int ge) {
            if (s >= tot) return;
            int task = (s >= Bn) ? 1 : 0;
            float Z, tlogit;
            bool cor;
            if (((o | c) & 3) == 0 && c <= BUFE) {
                const float4* sb = (const float4*)&ring[w][p][0];
                int c4 = c >> 2;
                float s0 = 0.f, s1 = 0.f, s2 = 0.f, s3 = 0.f;
                float m0 = NEGINF, m1 = NEGINF, m2 = NEGINF, m3 = NEGINF;
                #pragma unroll
                for (int k = 0; k < K4; ++k) {
                    int vi = lane + (k << 5);
                    if (vi < c4) {
                        float4 v = sb[vi];
                        s0 += ex2f(v.x * L2E);
                        s1 += ex2f(v.y * L2E);
                        s2 += ex2f(v.z * L2E);
                        s3 += ex2f(v.w * L2E);
                        m0 = fmaxf(m0, v.x);
                        m1 = fmaxf(m1, v.y);
                        m2 = fmaxf(m2, v.z);
                        m3 = fmaxf(m3, v.w);
                    }
                }
                Z = wsum((s0 + s1) + (s2 + s3));
                int gi = max(ge, 0);
                tlogit = ring[w][p][gi];
                float mym = fmaxf(fmaxf(m0, m1), fmaxf(m2, m3));
                cor = false;
                if (__all_sync(0xffffffffu, mym <= tlogit)) {   // rare
                    int myarg = 0x7fffffff;
                    #pragma unroll
                    for (int k = 0; k < K4; ++k) {
                        int vi = lane + (k << 5);
                        if (vi < c4) {
                            float4 v = sb[vi];
                            int e = vi << 2;
                            if (v.x == tlogit) myarg = min(myarg, e + 0);
                            if (v.y == tlogit) myarg = min(myarg, e + 1);
                            if (v.z == tlogit) myarg = min(myarg, e + 2);
                            if (v.w == tlogit) myarg = min(myarg, e + 3);
                        }
                    }
                    cor = (wmin(myarg) == ge);
                }
            } else {
                const float* ptr = task ? bar_logits : sys_logits;
                float sm = 0.0f, mymax = NEGINF;
                for (int i = lane; i < c; i += 32) {
                    float v = ptr[o + i];
                    sm += ex2f(v * L2E);
                    mymax = fmaxf(mymax, v);
                }
                Z = wsum(sm);
                tlogit = (ge >= 0) ? ptr[o + ge] : 0.0f;
                cor = false;
                if (__all_sync(0xffffffffu, mymax <= tlogit)) {
                    int arg = 0x7fffffff;
                    for (int i = lane; i < c; i += 32) {
                        if (ptr[o + i] == tlogit) arg = min(arg, i);
                    }
                    cor = (wmin(arg) == ge);
                }
            }
            if (lane == 0 && ge >= 0) {
                float ce = fmaf(lg2f(Z), LN2, -tlogit);   // ln(Z) - x_g
                int ci = cor ? 1 : 0;
                if (task) { ceb += ce; nvb += 1; cob += ci; }
                else      { ces += ce; nvs += 1; cos_ += ci; }
            }
        };

        // 2-deep software pipeline
        int s0 = gw, s1 = gw + W;
        int c0, o0, e0, c1, o1, e1;
        getmeta(0, c0, o0, e0);
        getmeta(1, c1, o1, e1);
        issue(0, s0, c0, o0);
        issue(1, s1, c1, o1);
        int p = 0, r = 2;
        while (s0 < tot) {
            int s2 = s1 + W;
            int c2, o2, e2;
            getmeta(r, c2, o2, e2);
            cpwait1();
            process(p, s0, c0, o0, e0);
            issue(p, s2, c2, o2);
            s0 = s1; c0 = c1; o0 = o1; e0 = e1;
            s1 = s2; c1 = c2; o1 = o2; e1 = e2;
            p ^= 1;
            ++r;
        }

        if (lane == 0) {
            s_ce[0][w] = ces; s_ce[1][w] = ceb;
            s_nv[0][w] = nvs; s_nv[1][w] = nvb;
            s_co[0][w] = cos_; s_co[1][w] = cob;
        }
        __syncthreads();
        if (t == 0) {
            float tce_s = 0.0f, tce_b = 0.0f;
            int tnv_s = 0, tco_s = 0, tnv_b = 0, tco_b = 0;
            #pragma unroll
            for (int i = 0; i < NWARP; ++i) {
                tce_s += s_ce[0][i]; tce_b += s_ce[1][i];
                tnv_s += s_nv[0][i]; tnv_b += s_nv[1][i];
                tco_s += s_co[0][i]; tco_b += s_co[1][i];
            }
            g_part_ce_s[cta] = (double)tce_s;
            g_part_ce_b[cta] = (double)tce_b;
            g_part_cnt[cta] = make_uint2(
                (unsigned int)tnv_s | ((unsigned int)tco_s << 16),
                (unsigned int)tnv_b | ((unsigned int)tco_b << 16));
        }
    }

    // ---------------- ticket + last-CTA finalize ----------------
    __syncthreads();
    __threadfence();
    if (t == 0) ticket = atomicAdd(&g_done, 1u);
    __syncthreads();
    if (ticket != gridDim.x - 1) return;

    if (t == 0) { g_done = 0; g_scan_done = 0; }

    double ce_s = 0, ce_b = 0, sq = 0, ns = 0;
    int nv_s = 0, co_s = 0, nv_b = 0, co_b = 0;

    for (int i = t; i < grid; i += 256) {
        ce_s += __ldcg(&g_part_ce_s[i]);
        ce_b += __ldcg(&g_part_ce_b[i]);
        uint2 pc = __ldcg(&g_part_cnt[i]);
        nv_s += pc.x & 0xffff; co_s += pc.x >> 16;
        nv_b += pc.y & 0xffff; co_b += pc.y >> 16;
        sq += __ldcg(&g_note_sq[i]);
        ns += __ldcg(&g_note_ns[i]);
    }

    ce_s = blk_sum256(ce_s, sbuf);
    double dnv_s = blk_sum256((double)nv_s, sbuf);
    double dco_s = blk_sum256((double)co_s, sbuf);
    ce_b = blk_sum256(ce_b, sbuf);
    double dnv_b = blk_sum256((double)nv_b, sbuf);
    double dco_b = blk_sum256((double)co_b, sbuf);
    sq = blk_sum256(sq, sbuf);
    ns = blk_sum256(ns, sbuf);

    if (t == 0) {
        double sys_loss  = ce_s / fmax(dnv_s, 1.0);
        double bar_loss  = ce_b / fmax(dnv_b, 1.0);
        double note_loss = (ns > 0.0) ? sq / fmax(ns, 1.0) : 0.0;

        float lvs = lv_sys[0], lvb = lv_bar[0], lvn = lv_note[0];
        float ps = expf(-lvs), pb = expf(-lvb), pn = expf(-lvn);

        double loss = 0.5 * (double)ps * sys_loss + 0.5 * (double)lvs
                    + 0.5 * (double)pb * bar_loss + 0.5 * (double)lvb
                    + 0.5 * (double)pn * note_loss + 0.5 * (double)lvn;

        out[0] = (float)loss;
        out[1] = (float)sys_loss;
        out[2] = (float)bar_loss;
        out[3] = (float)note_loss;
        out[4] = (float)(dco_s / fmax(dnv_s, 1.0));
        out[5] = (float)(dco_b / fmax(dnv_b, 1.0));
        out[6] = ps;
        out[7] = pb;
        out[8] = pn;
    }
}

// ---------------------------------------------------------------------------
extern "C" void kernel_launch(void* const* d_in, const int* in_sizes, int n_in,
                              void* d_out, int out_size) {
    const float* sys_logits = (const float*)d_in[0];
    const int*   sys_counts = (const int*)d_in[1];
    const float* bar_logits = (const float*)d_in[2];
    const int*   bar_counts = (const int*)d_in[3];
    const float* notep      = (const float*)d_in[4];
    const int*   gt_sys     = (const int*)d_in[5];
    const int*   gt_bar     = (const int*)d_in[6];
    const float* gtnote     = (const float*)d_in[7];
    const int*   valid      = (const int*)d_in[8];
    const float* lvs        = (const float*)d_in[9];
    const float* lvb        = (const float*)d_in[10];
    const float* lvn        = (const float*)d_in[11];

    int Bn = in_sizes[1];
    if (Bn > MAXB) Bn = MAXB;

    int grid = 148 * 4;                    // one wave at 4 CTAs/SM
    if (grid > MAXCTA) grid = MAXCTA;

    fused_kernel<<<grid, 256>>>(
        sys_logits, bar_logits, sys_counts, bar_counts, gt_sys, gt_bar, valid,
        notep, gtnote, lvs, lvb, lvn, Bn, (float*)d_out);
}